// round 15
// baseline (speedup 1.0000x reference)
#include <cuda_runtime.h>
#include <cuda_bf16.h>
#include <cstdint>
#include <cstddef>

#define T_STEPS 1024
#define BATCH   256
#define IDIM    128
#define HDIM    128
#define NCLS    18
#define G4      (4*HDIM)              /* 512 */
#define M_TOT   (T_STEPS*BATCH)       /* 262144 */

typedef unsigned long long ull;

/* Scratch (allocation-free rule: __device__ globals). */
__device__ float g_P[(size_t)M_TOT * G4];   /* 512 MB pre-gates */
__device__ float g_h[(size_t)M_TOT * HDIM]; /* 128 MB h_all    */
/* bf16 hi/mid splits of X and W_ih (written by k0) */
__device__ __nv_bfloat16 g_Xh[(size_t)M_TOT * IDIM];
__device__ __nv_bfloat16 g_Xm[(size_t)M_TOT * IDIM];
__device__ __nv_bfloat16 g_Wh[G4 * IDIM];
__device__ __nv_bfloat16 g_Wm[G4 * IDIM];

/* packed f32x2 FMA helpers (lstm/fc) */
__device__ __forceinline__ void ffma2(ull& d, ull a, ull b) {
    asm("fma.rn.f32x2 %0, %1, %2, %0;" : "+l"(d) : "l"(a), "l"(b));
}
__device__ __forceinline__ float hsum2(ull v) {
    float2 f = *(float2*)&v;
    return f.x + f.y;
}
__device__ __forceinline__ float fast_tanh(float x) {
    x = fminf(15.f, fmaxf(-15.f, x));
    float e = __expf(2.f * x);
    return (e - 1.f) * __frcp_rn(e + 1.f);
}
__device__ __forceinline__ float fast_sig(float x) {
    return __frcp_rn(1.f + __expf(-x));
}

/* ---- tensor core helpers (PTX-standard, compile on compute_103) ---- */
__device__ __forceinline__ void mma_bf16(float4& d, uint4 a, uint2 b) {
    asm volatile(
        "mma.sync.aligned.m16n8k16.row.col.f32.bf16.bf16.f32 "
        "{%0,%1,%2,%3}, {%4,%5,%6,%7}, {%8,%9}, {%0,%1,%2,%3};"
        : "+f"(d.x), "+f"(d.y), "+f"(d.z), "+f"(d.w)
        : "r"(a.x), "r"(a.y), "r"(a.z), "r"(a.w), "r"(b.x), "r"(b.y));
}
__device__ __forceinline__ void ldm4(uint4& r, uint32_t addr) {
    asm volatile("ldmatrix.sync.aligned.m8n8.x4.shared.b16 {%0,%1,%2,%3}, [%4];"
                 : "=r"(r.x), "=r"(r.y), "=r"(r.z), "=r"(r.w) : "r"(addr));
}
__device__ __forceinline__ uint32_t smem_u32(const void* p) {
    uint32_t a;
    asm("{ .reg .u64 t; cvta.to.shared.u64 t, %1; cvt.u32.u64 %0, t; }"
        : "=r"(a) : "l"(p));
    return a;
}
__device__ __forceinline__ ull gaddr(const void* p) {
    ull a; asm("cvta.to.global.u64 %0, %1;" : "=l"(a) : "l"(p)); return a;
}
#define CP_ASYNC16(dst, src) \
    asm volatile("cp.async.cg.shared.global [%0], [%1], 16;" :: "r"(dst), "l"(src))
#define CP_COMMIT() asm volatile("cp.async.commit_group;" ::: "memory")
#define CP_WAIT(n)  asm volatile("cp.async.wait_group %0;" :: "n"(n) : "memory")

/* ------------------------------------------------------------------ */
/* Kernel 0: split X, W_ih into bf16 hi/mid (x = hi + mid + O(2^-16)) */
/* ------------------------------------------------------------------ */
#define X_F4 8388608                  /* M_TOT*IDIM/4 */
#define W_F4 16384                    /* G4*IDIM/4    */

__global__ __launch_bounds__(256) void k0_split(
    const float* __restrict__ X, const float* __restrict__ Wih)
{
    size_t i4 = (size_t)blockIdx.x * 256 + threadIdx.x;
    float4 v;
    __nv_bfloat16 *dh, *dm;
    size_t e;
    if (i4 < X_F4) {
        v = ((const float4*)X)[i4];
        e = i4 * 4; dh = g_Xh; dm = g_Xm;
    } else {
        size_t j = i4 - X_F4;
        if (j >= W_F4) return;
        v = ((const float4*)Wih)[j];
        e = j * 4; dh = g_Wh; dm = g_Wm;
    }
    float xs[4] = {v.x, v.y, v.z, v.w};
    __nv_bfloat16 h[4], m[4];
#pragma unroll
    for (int i = 0; i < 4; i++) {
        h[i] = __float2bfloat16_rn(xs[i]);
        float r = xs[i] - __bfloat162float(h[i]);
        m[i] = __float2bfloat16_rn(r);
    }
    __nv_bfloat162 h01, h23, m01, m23;
    h01.x = h[0]; h01.y = h[1]; h23.x = h[2]; h23.y = h[3];
    m01.x = m[0]; m01.y = m[1]; m23.x = m[2]; m23.y = m[3];
    *(uint2*)(dh + e) = make_uint2(*(uint32_t*)&h01, *(uint32_t*)&h23);
    *(uint2*)(dm + e) = make_uint2(*(uint32_t*)&m01, *(uint32_t*)&m23);
}

/* ------------------------------------------------------------------ */
/* Kernel 1: P = X @ W_ih^T + (b_ih+b_hh), bf16 3-term m16n8k16.      */
/* (hh + hm + mh; mm term ~2^-16, dropped.)                           */
/* CTA 128M x 64N; K 4 stages of 32, cp.async double-buffered.        */
/* ------------------------------------------------------------------ */
#define K1_A_LVL   10240              /* 128*80 */
#define K1_B_BASE  20480
#define K1_B_LVL   5120               /* 64*80  */
#define K1_STAGE   30720
#define K1_SMEM    (2 * K1_STAGE)     /* 61440  */

__device__ __forceinline__ void k1_issue(
    uint32_t sbase, int m0, int n0, int ks, int tid)
{
#pragma unroll
    for (int i = 0; i < 4; i++) {
        int v = tid + 256 * i;
        int lvl = v >> 9, rem = v & 511;
        int r = rem >> 2, g = rem & 3;
        const __nv_bfloat16* src = (lvl ? g_Xm : g_Xh)
            + ((size_t)(m0 + r) * IDIM + ks * 32 + g * 8);
        CP_ASYNC16(sbase + lvl * K1_A_LVL + r * 80 + g * 16, gaddr(src));
    }
#pragma unroll
    for (int i = 0; i < 2; i++) {
        int v = tid + 256 * i;
        int lvl = v >> 8, rem = v & 255;
        int r = rem >> 2, g = rem & 3;
        const __nv_bfloat16* src = (lvl ? g_Wm : g_Wh)
            + ((size_t)(n0 + r) * IDIM + ks * 32 + g * 8);
        CP_ASYNC16(sbase + K1_B_BASE + lvl * K1_B_LVL + r * 80 + g * 16, gaddr(src));
    }
    CP_COMMIT();
}

__global__ __launch_bounds__(256) void k1_mma(
    const float* __restrict__ bih, const float* __restrict__ bhh)
{
    extern __shared__ char sm[];
    const uint32_t base = smem_u32(sm);

    const int tid  = threadIdx.x;
    const int lane = tid & 31;
    const int warp = tid >> 5;
    const int mwid = warp & 3;
    const int nwid = warp >> 2;
    const int m0 = blockIdx.y * 128;
    const int n0 = blockIdx.x * 64;

    const int lr = lane & 7, T = lane >> 3;
    const uint32_t aOff = (uint32_t)((mwid * 32 + (T & 1) * 8 + lr) * 80 + (T >> 1) * 16);
    const uint32_t bOff = (uint32_t)(K1_B_BASE + (nwid * 32 + (T >> 1) * 8 + lr) * 80 + (T & 1) * 16);

    float4 acc[2][4];
#pragma unroll
    for (int i = 0; i < 2; i++)
#pragma unroll
        for (int j = 0; j < 4; j++) acc[i][j] = make_float4(0.f, 0.f, 0.f, 0.f);

    k1_issue(base, m0, n0, 0, tid);
    k1_issue(base + K1_STAGE, m0, n0, 1, tid);

#pragma unroll
    for (int ks = 0; ks < 4; ks++) {
        if (ks == 3) { CP_WAIT(0); } else { CP_WAIT(1); }
        __syncthreads();

        const uint32_t bu = base + (uint32_t)(ks & 1) * K1_STAGE;
#pragma unroll
        for (int kc = 0; kc < 2; kc++) {
            uint4 Ah[2], Am[2];
#pragma unroll
            for (int mt = 0; mt < 2; mt++) {
                uint32_t a = bu + aOff + (uint32_t)(mt * 1280 + kc * 32);
                ldm4(Ah[mt], a);
                ldm4(Am[mt], a + K1_A_LVL);
            }
            uint4 Bh0, Bh1, Bm0, Bm1;
            {
                uint32_t b0 = bu + bOff + (uint32_t)(kc * 32);
                uint32_t b1 = b0 + 1280;
                ldm4(Bh0, b0);
                ldm4(Bh1, b1);
                ldm4(Bm0, b0 + K1_B_LVL);
                ldm4(Bm1, b1 + K1_B_LVL);
            }
            uint2 bh[4] = { make_uint2(Bh0.x, Bh0.y), make_uint2(Bh0.z, Bh0.w),
                            make_uint2(Bh1.x, Bh1.y), make_uint2(Bh1.z, Bh1.w) };
            uint2 bm[4] = { make_uint2(Bm0.x, Bm0.y), make_uint2(Bm0.z, Bm0.w),
                            make_uint2(Bm1.x, Bm1.y), make_uint2(Bm1.z, Bm1.w) };
#pragma unroll
            for (int mt = 0; mt < 2; mt++)
#pragma unroll
                for (int nt = 0; nt < 4; nt++) {
                    mma_bf16(acc[mt][nt], Ah[mt], bh[nt]);
                    mma_bf16(acc[mt][nt], Ah[mt], bm[nt]);
                    mma_bf16(acc[mt][nt], Am[mt], bh[nt]);
                }
        }

        if (ks < 2) {
            __syncthreads();
            k1_issue(base + (uint32_t)(ks & 1) * K1_STAGE, m0, n0, ks + 2, tid);
        }
    }

    const int g = lane >> 2, t = lane & 3;
#pragma unroll
    for (int mi = 0; mi < 2; mi++) {
        int mrow = m0 + (2 * mwid + mi) * 16 + g;
#pragma unroll
        for (int nt = 0; nt < 4; nt++) {
            int nc = n0 + (4 * nwid + nt) * 8 + 2 * t;
            float b0 = __ldg(&bih[nc])     + __ldg(&bhh[nc]);
            float b1 = __ldg(&bih[nc + 1]) + __ldg(&bhh[nc + 1]);
            float4 a = acc[mi][nt];
            *(float2*)&g_P[(size_t)mrow * G4 + nc] = make_float2(a.x + b0, a.y + b1);
            *(float2*)&g_P[(size_t)(mrow + 8) * G4 + nc] = make_float2(a.z + b0, a.w + b1);
        }
    }
}

/* ------------------------------------------------------------------ */
/* Kernel 2: recurrence (R5 exact, 2521-validated).                   */
/* ------------------------------------------------------------------ */
__global__ __launch_bounds__(256, 1) void k_lstm(
    const float* __restrict__ h0, const float* __restrict__ c0,
    const float* __restrict__ Whh, float* __restrict__ state_out,
    int write_state)
{
    extern __shared__ float sm2[];
    float* Wsm  = sm2;                  /* [512 rows][36]: k=96..127 */
    float* hbuf = Wsm + 512 * 36;
    float* gsm  = hbuf + 512;

    const int tid = threadIdx.x;
    const int b0  = blockIdx.x * 2;

    for (int idx = tid; idx < 512 * 8; idx += 256) {
        int row = idx >> 3, q = idx & 7;
        *(float4*)&Wsm[row * 36 + 4 * q] =
            *(const float4*)&Whh[(size_t)row * 128 + 96 + 4 * q];
    }

    ull w0[48], w1[48];
    {
        const ulonglong2* wg0 = (const ulonglong2*)(Whh + (size_t)tid * 128);
        const ulonglong2* wg1 = (const ulonglong2*)(Whh + (size_t)(tid + 256) * 128);
#pragma unroll
        for (int q = 0; q < 24; q++) {
            ulonglong2 t0 = wg0[q]; w0[2 * q] = t0.x; w0[2 * q + 1] = t0.y;
            ulonglong2 t1 = wg1[q]; w1[2 * q] = t1.x; w1[2 * q + 1] = t1.y;
        }
    }

    const int eb = tid >> 7, eu = tid & 127;
    float creg = c0[(b0 + eb) * HDIM + eu];
    float hlast = 0.f;
    hbuf[eb * 128 + eu] = h0[(b0 + eb) * HDIM + eu];
    __syncthreads();

    size_t ip = (size_t)b0 * G4;
    float p00 = g_P[ip + tid];
    float p01 = g_P[ip + 512 + tid];
    float p10 = g_P[ip + tid + 256];
    float p11 = g_P[ip + 512 + tid + 256];

    const ulonglong2* ws0 = (const ulonglong2*)(Wsm + tid * 36);
    const ulonglong2* ws1 = (const ulonglong2*)(Wsm + (tid + 256) * 36);

    for (int t = 0; t < T_STEPS; t++) {
        float q00 = p00, q01 = p01, q10 = p10, q11 = p11;
        ip += (size_t)BATCH * G4;
        if (t < T_STEPS - 1) {
            p00 = g_P[ip + tid];
            p01 = g_P[ip + 512 + tid];
            p10 = g_P[ip + tid + 256];
            p11 = g_P[ip + 512 + tid + 256];
        }

        const ulonglong2* hA = (const ulonglong2*)(hbuf + (t & 1) * 256);
        const ulonglong2* hB = hA + 32;

        ull a00 = 0ull, a01 = 0ull, a10 = 0ull, a11 = 0ull;

#pragma unroll
        for (int q = 0; q < 24; q++) {
            ulonglong2 ha = hA[q];
            ulonglong2 hb = hB[q];
            ffma2(a00, w0[2 * q],     ha.x); ffma2(a00, w0[2 * q + 1], ha.y);
            ffma2(a01, w0[2 * q],     hb.x); ffma2(a01, w0[2 * q + 1], hb.y);
            ffma2(a10, w1[2 * q],     ha.x); ffma2(a10, w1[2 * q + 1], ha.y);
            ffma2(a11, w1[2 * q],     hb.x); ffma2(a11, w1[2 * q + 1], hb.y);
        }
#pragma unroll
        for (int q = 0; q < 8; q++) {
            ulonglong2 ha = hA[24 + q];
            ulonglong2 hb = hB[24 + q];
            ulonglong2 wa = ws0[q];
            ulonglong2 wb = ws1[q];
            ffma2(a00, wa.x, ha.x); ffma2(a00, wa.y, ha.y);
            ffma2(a01, wa.x, hb.x); ffma2(a01, wa.y, hb.y);
            ffma2(a10, wb.x, ha.x); ffma2(a10, wb.y, ha.y);
            ffma2(a11, wb.x, hb.x); ffma2(a11, wb.y, hb.y);
        }

        *(float2*)&gsm[2 * tid]         = make_float2(q00 + hsum2(a00), q01 + hsum2(a01));
        *(float2*)&gsm[2 * (tid + 256)] = make_float2(q10 + hsum2(a10), q11 + hsum2(a11));
        __syncthreads();

        {
            float gi = gsm[2 * eu + eb];
            float gf = gsm[2 * (128 + eu) + eb];
            float gg = gsm[2 * (256 + eu) + eb];
            float go = gsm[2 * (384 + eu) + eb];
            float iv = fast_sig(gi);
            float fv = fast_sig(gf);
            float gv = fast_tanh(gg);
            float ov = fast_sig(go);
            creg = fv * creg + iv * gv;
            float h = ov * fast_tanh(creg);
            hlast = h;
            hbuf[((t + 1) & 1) * 256 + eb * 128 + eu] = h;
            g_h[((size_t)t * BATCH + b0 + eb) * HDIM + eu] = h;
        }
        __syncthreads();
    }

    if (write_state) {
        state_out[(b0 + eb) * HDIM + eu] = hlast;
        state_out[BATCH * HDIM + (b0 + eb) * HDIM + eu] = creg;
    }
}

/* ------------------------------------------------------------------ */
/* Kernel 3: out = h_all @ fc_W^T + fc_b.                             */
/* 2048 blocks x 128 thr; coalesced g_h tile -> SMEM (pad 132), then  */
/* row-per-thread from SMEM (33t mod 8 distinct -> conflict-free).    */
/* ------------------------------------------------------------------ */
#define FC_HPAD 132
#define FC_SMEM ((128 * FC_HPAD + NCLS * HDIM + 32) * 4)

__global__ __launch_bounds__(128) void k_fc(
    const float* __restrict__ fcW, const float* __restrict__ fcb,
    float* __restrict__ out)
{
    extern __shared__ float fs[];
    float* Hs  = fs;                       /* [128][132] */
    float* Ws  = fs + 128 * FC_HPAD;       /* [18][128]  */
    float* bsh = Ws + NCLS * HDIM;

    const int tid = threadIdx.x;
    const size_t m0 = (size_t)blockIdx.x * 128;

    const float4* gsrc = (const float4*)(g_h + m0 * HDIM);
#pragma unroll
    for (int i = 0; i < 32; i++) {
        int v = tid + 128 * i;
        int r = v >> 5, c = v & 31;
        *(float4*)&Hs[r * FC_HPAD + c * 4] = gsrc[v];
    }
    for (int i = tid; i < NCLS * HDIM / 4; i += 128)
        *(float4*)&Ws[i * 4] = *(const float4*)&fcW[i * 4];
    if (tid < NCLS) bsh[tid] = fcb[tid];
    __syncthreads();

    ull acc[NCLS];
#pragma unroll
    for (int c = 0; c < NCLS; c++) acc[c] = 0ull;

#pragma unroll 4
    for (int q = 0; q < 32; q++) {
        ulonglong2 h = *(const ulonglong2*)&Hs[tid * FC_HPAD + 4 * q];
#pragma unroll
        for (int c = 0; c < NCLS; c++) {
            ulonglong2 w = *(const ulonglong2*)&Ws[c * HDIM + 4 * q];
            ffma2(acc[c], w.x, h.x);
            ffma2(acc[c], w.y, h.y);
        }
    }
    float* po = out + (m0 + tid) * NCLS;
#pragma unroll
    for (int c = 0; c < NCLS; c++) po[c] = bsh[c] + hsum2(acc[c]);
}

/* ------------------------------------------------------------------ */
extern "C" void kernel_launch(void* const* d_in, const int* in_sizes, int n_in,
                              void* d_out, int out_size)
{
    const float* X   = (const float*)d_in[0];
    const float* hid = (const float*)d_in[1];
    const float* cel = (const float*)d_in[2];
    const float* Wih = (const float*)d_in[3];
    const float* Whh = (const float*)d_in[4];
    const float* bih = (const float*)d_in[5];
    const float* bhh = (const float*)d_in[6];
    const float* fcW = (const float*)d_in[7];
    const float* fcb = (const float*)d_in[8];
    float* out = (float*)d_out;

    const int smem2 = (512 * 36 + 512 + 1024) * 4;            /* 79872 */
    cudaFuncSetAttribute(k1_mma, cudaFuncAttributeMaxDynamicSharedMemorySize, K1_SMEM);
    cudaFuncSetAttribute(k_lstm, cudaFuncAttributeMaxDynamicSharedMemorySize, smem2);
    cudaFuncSetAttribute(k_fc,   cudaFuncAttributeMaxDynamicSharedMemorySize, FC_SMEM);

    k0_split<<<(X_F4 + W_F4) / 256, 256>>>(X, Wih);
    k1_mma<<<dim3(G4 / 64, M_TOT / 128), 256, K1_SMEM>>>(bih, bhh);

    const int main_elems = T_STEPS * BATCH * NCLS;
    int wstate = (out_size >= main_elems + 2 * BATCH * HDIM) ? 1 : 0;
    float* state_out = out + (size_t)main_elems;
    k_lstm<<<BATCH / 2, 256, smem2>>>(hid, cel, Whh, state_out, wstate);

    k_fc<<<M_TOT / 128, 128, FC_SMEM>>>(fcW, fcb, out);
}